// round 9
// baseline (speedup 1.0000x reference)
#include <cuda_runtime.h>

// Problem geometry (fixed by the dataset):
//   y: [1,512,512,8,8] f32 = 16,777,216 elems
//   c: [2,256,256,8,8] f32 =  8,388,608 elems (2 channels x 4,194,304)
// Output: y then c concatenated, 25,165,824 f32.
//
// Persistent single-wave kernel: 1,184 blocks (148 SMs x 8) x 256 threads.
// Work = 6,144 chunks of 1024 consecutive float4s (chunks [0,4096) = y,
// [4096,6144) = c; c chunk ch = (chunk-4096)>>10). Each block grid-strides
// chunk = blockIdx.x + k*1184, processing 4 front-batched float4s/thread per
// chunk (measured MLP optimum: 2->30.3us, 4->27.3-28.2us, 8->33.3us).
// All blocks are co-resident (one wave), so:
//   - no wave transitions / ragged tail,
//   - the DC-reduction spin is unconditionally deadlock-free.
// Blocks [0,512) first do the DC reduction (one clamped DC/thread) into
// g_dc_sum + bump g_red_cnt. Before a block's FIRST c chunk it polls the
// counter once (thread 0) and caches both channel means in shared memory.
// Bulk stream is touch-once: __ldcs/__stcs. Last finished block resets the
// globals for the next graph replay.

#define CMIN  (-1024.0f)
#define CMAX  (1016.0f)
#define FACT  (1.9f)

static const int   NY4       = 4194304;    // y float4 count
static const int   N_CHUNK   = 6144;       // total 1024-float4 chunks
static const int   N_Y_CHUNK = 4096;       // y chunks
static const int   GRID      = 1184;       // 148 SMs * 8 blocks
static const int   N_RED_BLK = 512;        // reducer blocks (256 DC each)
static const float INV_CNT   = 1.0f / 65536.0f;

__device__ float g_dc_sum[2];
__device__ int   g_red_cnt;
__device__ int   g_done;

__device__ __forceinline__ float clampf(float v) {
    return fminf(fmaxf(v, CMIN), CMAX);
}

__device__ __forceinline__ float4 y_op(float4 v) {
    v.x = clampf(clampf(v.x) * FACT);
    v.y = clampf(clampf(v.y) * FACT);
    v.z = clampf(clampf(v.z) * FACT);
    v.w = clampf(clampf(v.w) * FACT);
    return v;
}

__device__ __forceinline__ float4 c_op(float4 v, int j, float blend) {
    v.x = clampf(v.x) * FACT;
    v.y = clampf(v.y) * FACT;
    v.z = clampf(v.z) * FACT;
    v.w = clampf(v.w) * FACT;
    if ((j & 15) == 0) v.x += blend;   // elem j*4 is a DC coeff (idx%64==0)
    v.x = clampf(v.x);
    v.y = clampf(v.y);
    v.z = clampf(v.z);
    v.w = clampf(v.w);
    return v;
}

__global__ void __launch_bounds__(256) fused_kernel(
    const float4* __restrict__ y, const float4* __restrict__ c,
    float4* __restrict__ oy, float4* __restrict__ oc)
{
    __shared__ float s_warp[8];
    __shared__ float s_mean[2];

    // ---- Extra duty: DC reduction on first 512 blocks ----
    if (blockIdx.x < N_RED_BLK) {
        int idx = blockIdx.x * 256 + threadIdx.x;   // 0 .. 131071
        int ch  = idx >> 16;                        // constant per block
        // DC coeff idx lives at c-element idx*64 == float4 idx*16, comp .x
        // Default (caching) load: c chunks re-read these lines later.
        float v = clampf(c[idx * 16].x);

        #pragma unroll
        for (int off = 16; off > 0; off >>= 1)
            v += __shfl_down_sync(0xffffffffu, v, off);
        if ((threadIdx.x & 31) == 0) s_warp[threadIdx.x >> 5] = v;
        __syncthreads();
        if (threadIdx.x < 8) {
            float w = s_warp[threadIdx.x];
            #pragma unroll
            for (int off = 4; off > 0; off >>= 1)
                w += __shfl_down_sync(0xffu, w, off);
            if (threadIdx.x == 0) {
                atomicAdd(&g_dc_sum[ch], w);
                __threadfence();
                atomicAdd(&g_red_cnt, 1);
            }
        }
        __syncthreads();    // s_warp safely reusable; block proceeds to stream
    }

    bool  have_mean = false;
    float blend0 = 0.0f, blend1 = 0.0f;

    for (int chunk = blockIdx.x; chunk < N_CHUNK; chunk += GRID) {
        int i0 = chunk * 1024 + threadIdx.x;

        if (chunk < N_Y_CHUNK) {
            // ---- y chunk: 4 front-batched streaming loads ----
            float4 a = __ldcs(&y[i0]);
            float4 b = __ldcs(&y[i0 + 256]);
            float4 d = __ldcs(&y[i0 + 512]);
            float4 e = __ldcs(&y[i0 + 768]);
            __stcs(&oy[i0],       y_op(a));
            __stcs(&oy[i0 + 256], y_op(b));
            __stcs(&oy[i0 + 512], y_op(d));
            __stcs(&oy[i0 + 768], y_op(e));
        } else {
            // ---- c chunk ----
            // Lazily fetch both channel means once per block. Condition is
            // block-uniform (all threads share the same chunk sequence).
            if (!have_mean) {
                if (threadIdx.x == 0) {
                    while (*((volatile int*)&g_red_cnt) != N_RED_BLK) { }
                    s_mean[0] = (*((volatile float*)&g_dc_sum[0])) * INV_CNT;
                    s_mean[1] = (*((volatile float*)&g_dc_sum[1])) * INV_CNT;
                }
                __syncthreads();
                blend0 = (1.0f - FACT) * s_mean[0];
                blend1 = (1.0f - FACT) * s_mean[1];
                have_mean = true;
            }
            int   j0    = i0 - NY4;                       // 0 .. NC4-1
            float blend = ((chunk - N_Y_CHUNK) >> 10) ? blend1 : blend0;

            float4 a = __ldcs(&c[j0]);
            float4 b = __ldcs(&c[j0 + 256]);
            float4 d = __ldcs(&c[j0 + 512]);
            float4 e = __ldcs(&c[j0 + 768]);
            __stcs(&oc[j0],       c_op(a, j0,       blend));
            __stcs(&oc[j0 + 256], c_op(b, j0 + 256, blend));
            __stcs(&oc[j0 + 512], c_op(d, j0 + 512, blend));
            __stcs(&oc[j0 + 768], c_op(e, j0 + 768, blend));
        }
    }

    // ---- reset globals for next graph replay (last finished block) ----
    __syncthreads();
    if (threadIdx.x == 0) {
        int old = atomicAdd(&g_done, 1);
        if (old == GRID - 1) {
            *((volatile float*)&g_dc_sum[0]) = 0.0f;
            *((volatile float*)&g_dc_sum[1]) = 0.0f;
            *((volatile int*)&g_red_cnt)     = 0;
            *((volatile int*)&g_done)        = 0;
            __threadfence();
        }
    }
}

extern "C" void kernel_launch(void* const* d_in, const int* in_sizes, int n_in,
                              void* d_out, int out_size) {
    const float4* y = (const float4*)d_in[0];
    const float4* c = (const float4*)d_in[1];
    float4* oy = (float4*)d_out;
    float4* oc = (float4*)d_out + NY4;

    fused_kernel<<<GRID, 256>>>(y, c, oy, oc);
}